// round 13
// baseline (speedup 1.0000x reference)
#include <cuda_runtime.h>
#include <cuda_bf16.h>
#include <math.h>

#define B_  256
#define T_  500
#define BT_ 128000
#define DK_ 128
#define DV_ 256
#define M_  50
#define LWP 64    // permuted softmax-weight row stride (floats)
#define KF_ 384
#define LDT 24    // smem tile row stride bf16 (48B, conflict-free ldmatrix)

#define NQA 100001  // qa_tab rows
#define NQT 50001   // q_tab rows

// ---------------- scratch ----------------
__device__ unsigned g_EA[(size_t)BT_ * DV_];          // (-e, a) bf16x2
__device__ float g_Wt[(size_t)BT_ * LWP];             // permuted softmax weights
__device__ __nv_bfloat16 g_READ[(size_t)BT_ * DV_];
__device__ float g_part[2 * (BT_ / 128)];
__device__ __align__(16) __nv_bfloat16 g_qa[(size_t)NQA * DV_];
__device__ __align__(16) __nv_bfloat16 g_qt[(size_t)NQT * DK_];
__device__ __align__(16) __nv_bfloat16 g_We[DV_ * DV_];
__device__ __align__(16) __nv_bfloat16 g_Wa[DV_ * DV_];
__device__ __align__(16) __nv_bfloat16 g_Wr[DK_ * KF_];
__device__ __align__(16) __nv_bfloat16 g_Mkp[64 * DK_];

// ---------------- helpers ----------------
__device__ __forceinline__ unsigned pack_bf16(float lo, float hi) {
  unsigned r;
  asm("cvt.rn.bf16x2.f32 %0, %1, %2;" : "=r"(r) : "f"(hi), "f"(lo));
  return r;
}
__device__ __forceinline__ void mma_bf16(float* c, const unsigned* a, const unsigned* b) {
  asm volatile(
      "mma.sync.aligned.m16n8k16.row.col.f32.bf16.bf16.f32 "
      "{%0,%1,%2,%3}, {%4,%5,%6,%7}, {%8,%9}, {%0,%1,%2,%3};\n"
      : "+f"(c[0]), "+f"(c[1]), "+f"(c[2]), "+f"(c[3])
      : "r"(a[0]), "r"(a[1]), "r"(a[2]), "r"(a[3]), "r"(b[0]), "r"(b[1]));
}
__device__ __forceinline__ void ldsm_x4(unsigned& r0, unsigned& r1, unsigned& r2,
                                        unsigned& r3, unsigned addr) {
  asm volatile(
      "ldmatrix.sync.aligned.m8n8.x4.shared.b16 {%0,%1,%2,%3}, [%4];"
      : "=r"(r0), "=r"(r1), "=r"(r2), "=r"(r3) : "r"(addr));
}
__device__ __forceinline__ unsigned smem_u32(const void* p) {
  return (unsigned)__cvta_generic_to_shared(p);
}
__device__ __forceinline__ void cp16(unsigned dst, const void* src) {
  asm volatile("cp.async.cg.shared.global [%0], [%1], 16;" :: "r"(dst), "l"(src));
}
#define CP_COMMIT() asm volatile("cp.async.commit_group;")
#define CP_WAIT1()  asm volatile("cp.async.wait_group 1;")

__device__ __forceinline__ unsigned long long pack2(float lo, float hi) {
  unsigned long long r;
  asm("mov.b64 %0, {%1,%2};" : "=l"(r) : "f"(lo), "f"(hi));
  return r;
}
__device__ __forceinline__ unsigned long long fma2(unsigned long long a,
                                                   unsigned long long b,
                                                   unsigned long long c) {
  unsigned long long d;
  asm("fma.rn.f32x2 %0, %1, %2, %3;" : "=l"(d) : "l"(a), "l"(b), "l"(c));
  return d;
}
__device__ __forceinline__ float2 unpack2(unsigned long long v) {
  float2 f;
  asm("mov.b64 {%0,%1}, %2;" : "=f"(f.x), "=f"(f.y) : "l"(v));
  return f;
}

// ---------------- prep: all f32 -> bf16 in ONE launch ----------------
__global__ void __launch_bounds__(256) cvt_all(
    const float* __restrict__ qa, const float* __restrict__ qt,
    const float* __restrict__ We, const float* __restrict__ Wa,
    const float* __restrict__ Wr, const float* __restrict__ Mk) {
  const long N0 = (long)(NQA) * DV_ / 4;
  const long N1 = N0 + (long)(NQT) * DK_ / 4;
  const long N2 = N1 + 16384;
  const long N3 = N2 + 16384;
  const long N4 = N3 + 12288;
  const long N5 = N4 + 2048;
  long i = (long)blockIdx.x * 256 + threadIdx.x;
  if (i >= N5) return;
  const float* src;
  uint2* dst;
  long j;
  if (i < N0) { src = qa; dst = (uint2*)g_qa; j = i; }
  else if (i < N1) { src = qt; dst = (uint2*)g_qt; j = i - N0; }
  else if (i < N2) { src = We; dst = (uint2*)g_We; j = i - N1; }
  else if (i < N3) { src = Wa; dst = (uint2*)g_Wa; j = i - N2; }
  else if (i < N4) { src = Wr; dst = (uint2*)g_Wr; j = i - N3; }
  else {
    j = i - N4;
    float4 v = (j < (M_ * DK_) / 4) ? ((const float4*)Mk)[j]
                                    : make_float4(0.f, 0.f, 0.f, 0.f);
    ((uint2*)g_Mkp)[j] = make_uint2(pack_bf16(v.x, v.y), pack_bf16(v.z, v.w));
    return;
  }
  float4 v = ((const float4*)src)[j];
  dst[j] = make_uint2(pack_bf16(v.x, v.y), pack_bf16(v.z, v.w));
}

// ================= gemm_ea: cp.async 3-stage, E+A one block =================
// stores (-e, a) packed bf16x2
__global__ void __launch_bounds__(256) gemm_ea_bf16(
    const int* __restrict__ idx,
    const float* __restrict__ be, const float* __restrict__ ba) {
  constexpr int BK = 16, KT = DV_ / BK;
  constexpr int MT = 4;
  constexpr int STGB = 128 * LDT * 2;

  __shared__ __align__(16) __nv_bfloat16 As[3 * 128 * LDT];
  __shared__ __align__(16) __nv_bfloat16 Bs[3 * 128 * LDT];
  __shared__ int rowA[128];

  const int tid = threadIdx.x;
  const int wid = tid >> 5, lane = tid & 31;
  const int wm = wid >> 2, wn = wid & 3;
  const int r = lane >> 2, c = lane & 3;
  const int bm = blockIdx.y * 128;
  const int nrow0 = blockIdx.x * 64;

  for (int i = tid; i < 128; i += 256) rowA[i] = idx[bm + i];
  __syncthreads();

  float accE[MT][2][4], accA[MT][2][4];
#pragma unroll
  for (int i = 0; i < MT; i++)
#pragma unroll
    for (int j = 0; j < 2; j++)
#pragma unroll
      for (int q = 0; q < 4; q++) { accE[i][j][q] = 0.f; accA[i][j][q] = 0.f; }

  const unsigned aBase = smem_u32(As);
  const unsigned bBase = smem_u32(Bs);
  const int gRow = tid >> 1, gHalf = tid & 1;
  const __nv_bfloat16* aSrc = g_qa + (size_t)rowA[gRow] * DV_ + gHalf * 8;
  const __nv_bfloat16* bSrc =
      (gRow < 64) ? g_We + (size_t)(nrow0 + gRow) * DV_ + gHalf * 8
                  : g_Wa + (size_t)(nrow0 + gRow - 64) * DV_ + gHalf * 8;
  const unsigned aDst0 = aBase + gRow * 48 + gHalf * 16;
  const unsigned bDst0 = bBase + gRow * 48 + gHalf * 16;

  auto issueT = [&](int kt, int stg) {
    cp16(aDst0 + stg * STGB, aSrc + kt * BK);
    cp16(bDst0 + stg * STGB, bSrc + kt * BK);
    CP_COMMIT();
  };

  issueT(0, 0);
  issueT(1, 1);
  CP_WAIT1();
  __syncthreads();

  const int aRow = wm * 64 + (lane & 15);
  const int aColB = (lane & 16) ? 16 : 0;
  const int bRowE = wn * 16 + ((lane >> 4) << 3) + (lane & 7);
  const int bColB = (lane & 8) ? 16 : 0;

  for (int kt = 0; kt < KT; kt++) {
    const unsigned aS = aBase + (kt % 3) * STGB;
    const unsigned bS = bBase + (kt % 3) * STGB;
    unsigned af[MT][4], bfe[4], bfa[4];
#pragma unroll
    for (int mt = 0; mt < MT; mt++)
      ldsm_x4(af[mt][0], af[mt][1], af[mt][2], af[mt][3],
              aS + (aRow + mt * 16) * 48 + aColB);
    ldsm_x4(bfe[0], bfe[1], bfe[2], bfe[3], bS + bRowE * 48 + bColB);
    ldsm_x4(bfa[0], bfa[1], bfa[2], bfa[3], bS + (64 + bRowE) * 48 + bColB);
#pragma unroll
    for (int mt = 0; mt < MT; mt++) {
      mma_bf16(accE[mt][0], af[mt], &bfe[0]);
      mma_bf16(accE[mt][1], af[mt], &bfe[2]);
      mma_bf16(accA[mt][0], af[mt], &bfa[0]);
      mma_bf16(accA[mt][1], af[mt], &bfa[2]);
    }
    int nk = (kt + 2 < KT) ? kt + 2 : KT - 1;
    issueT(nk, (kt + 2) % 3);
    CP_WAIT1();
    __syncthreads();
  }

#pragma unroll
  for (int mt = 0; mt < MT; mt++) {
#pragma unroll
    for (int nt = 0; nt < 2; nt++) {
      int rowL = wm * 64 + mt * 16 + r;
      int ncol = nrow0 + wn * 16 + nt * 8 + 2 * c;
      float be0 = be[ncol], be1 = be[ncol + 1];
      float ba0 = ba[ncol], ba1 = ba[ncol + 1];
      float e0 = 1.f / (1.f + expf(-(accE[mt][nt][0] + be0)));
      float e1 = 1.f / (1.f + expf(-(accE[mt][nt][1] + be1)));
      float e2 = 1.f / (1.f + expf(-(accE[mt][nt][2] + be0)));
      float e3 = 1.f / (1.f + expf(-(accE[mt][nt][3] + be1)));
      float a0 = tanhf(accA[mt][nt][0] + ba0);
      float a1 = tanhf(accA[mt][nt][1] + ba1);
      float a2 = tanhf(accA[mt][nt][2] + ba0);
      float a3 = tanhf(accA[mt][nt][3] + ba1);
      *(uint2*)(g_EA + (size_t)(bm + rowL) * DV_ + ncol) =
          make_uint2(pack_bf16(-e0, a0), pack_bf16(-e1, a1));
      *(uint2*)(g_EA + (size_t)(bm + rowL + 8) * DV_ + ncol) =
          make_uint2(pack_bf16(-e2, a2), pack_bf16(-e3, a3));
    }
  }
}

// ================= logits GEMM + softmax: 4-class permuted-w output =========
// g_Wt row (64 floats): class c (=pair mod 4) occupies [c*16, c*16+2*Sc) where
// Sc = 7 for c=0 else 6. Pair p=4s+c maps w[2p],w[2p+1] -> pos c*16+2s, +1.
__global__ void __launch_bounds__(256) logits_softmax_bf16(
    const int* __restrict__ q_data) {
  constexpr int BK = 16, KT = DK_ / BK;
  constexpr int MT = 2, NT = 4;
  constexpr int STGA = 128 * LDT * 2;
  constexpr int STGB = 64 * LDT * 2;

  __shared__ __align__(16) __nv_bfloat16 As[3 * 128 * LDT];
  __shared__ __align__(16) __nv_bfloat16 Bs[3 * 64 * LDT];
  __shared__ int rowA[128];
  __shared__ float sLg[128][65];
  __shared__ float sInv[128];

  const int tid = threadIdx.x;
  const int wid = tid >> 5, lane = tid & 31;
  const int wm = wid >> 1, wn = wid & 1;
  const int r = lane >> 2, c = lane & 3;
  const int bm = blockIdx.x * 128;

  for (int i = tid; i < 128; i += 256) rowA[i] = q_data[bm + i];
  __syncthreads();

  float acc[MT][NT][4];
#pragma unroll
  for (int i = 0; i < MT; i++)
#pragma unroll
    for (int j = 0; j < NT; j++)
#pragma unroll
      for (int q = 0; q < 4; q++) acc[i][j][q] = 0.f;

  const unsigned aBase = smem_u32(As);
  const unsigned bBase = smem_u32(Bs);
  const int gRow = tid >> 1, gHalf = tid & 1;
  const __nv_bfloat16* aSrc = g_qt + (size_t)rowA[gRow] * DK_ + gHalf * 8;
  const __nv_bfloat16* bSrc = g_Mkp + (size_t)gRow * DK_ + gHalf * 8;
  const unsigned aDst0 = aBase + gRow * 48 + gHalf * 16;
  const unsigned bDst0 = bBase + gRow * 48 + gHalf * 16;

  auto issueT = [&](int kt, int stg) {
    cp16(aDst0 + stg * STGA, aSrc + kt * BK);
    if (tid < 128) cp16(bDst0 + stg * STGB, bSrc + kt * BK);
    CP_COMMIT();
  };

  issueT(0, 0);
  issueT(1, 1);
  CP_WAIT1();
  __syncthreads();

  const int aRow = wm * 32 + (lane & 15);
  const int aColB = (lane & 16) ? 16 : 0;
  const int bRow0 = wn * 32 + ((lane >> 4) << 3) + (lane & 7);
  const int bColB = (lane & 8) ? 16 : 0;

  for (int kt = 0; kt < KT; kt++) {
    const unsigned aS = aBase + (kt % 3) * STGA;
    const unsigned bS = bBase + (kt % 3) * STGB;
    unsigned af[MT][4], bf[NT][2];
#pragma unroll
    for (int mt = 0; mt < MT; mt++)
      ldsm_x4(af[mt][0], af[mt][1], af[mt][2], af[mt][3],
              aS + (aRow + mt * 16) * 48 + aColB);
#pragma unroll
    for (int p = 0; p < 2; p++)
      ldsm_x4(bf[2 * p][0], bf[2 * p][1], bf[2 * p + 1][0], bf[2 * p + 1][1],
              bS + (bRow0 + p * 16) * 48 + bColB);
#pragma unroll
    for (int mt = 0; mt < MT; mt++)
#pragma unroll
      for (int nt = 0; nt < NT; nt++) mma_bf16(acc[mt][nt], af[mt], bf[nt]);
    int nk = (kt + 2 < KT) ? kt + 2 : KT - 1;
    issueT(nk, (kt + 2) % 3);
    CP_WAIT1();
    __syncthreads();
  }

#pragma unroll
  for (int mt = 0; mt < MT; mt++) {
#pragma unroll
    for (int nt = 0; nt < NT; nt++) {
      int rowL = wm * 32 + mt * 16 + r;
      int colL = wn * 32 + nt * 8 + 2 * c;
      sLg[rowL][colL] = acc[mt][nt][0];
      sLg[rowL][colL + 1] = acc[mt][nt][1];
      sLg[rowL + 8][colL] = acc[mt][nt][2];
      sLg[rowL + 8][colL + 1] = acc[mt][nt][3];
    }
  }
  __syncthreads();

  if (tid < 128) {
    float mx = -1e30f;
#pragma unroll 10
    for (int j = 0; j < M_; j++) mx = fmaxf(mx, sLg[tid][j]);
    float s = 0.f;
#pragma unroll 10
    for (int j = 0; j < M_; j++) {
      float ev = expf(sLg[tid][j] - mx);
      sLg[tid][j] = ev;
      s += ev;
    }
    sInv[tid] = 1.f / s;
  }
  __syncthreads();

  // 4-class permuted coalesced write (pads = 0)
  for (int f = tid; f < 128 * LWP; f += 256) {
    int rowL = f >> 6;
    int pos = f & 63;
    int cls = pos >> 4;
    int o = pos & 15;
    int lim = (cls == 0) ? 14 : 12;
    float v = 0.f;
    if (o < lim) {
      int s = o >> 1;
      int p = 4 * s + cls;
      int j = 2 * p + (o & 1);
      v = sLg[rowL][j] * sInv[rowL];
    }
    g_Wt[(size_t)(bm + rowL) * LWP + pos] = v;
  }
}

// ------- scan: m-split x4 (thread (d, mh) owns pairs p == mh mod 4) -------
// block = 128 thr = 32 d-cols x 4 mh; grid = B_ * 8 (8 d-segments of 32)
__global__ void __launch_bounds__(128, 10) scan_kernel(
    const float* __restrict__ Mv0, const int* __restrict__ q_data) {
  const int b = blockIdx.x >> 3;
  const int dseg = blockIdx.x & 7;
  const int tid = threadIdx.x;
  const int wid = tid >> 5, lane = tid & 31;
  const int d = dseg * 32 + (tid >> 2);
  const int mh = tid & 3;
  const int np = (mh == 0) ? 7 : 6;  // owned pairs
  __shared__ __align__(16) float ws_all[4][64];
  float* ws = ws_all[wid];

  // mv[n] = pair p = 4n + mh (m rows 2p, 2p+1)
  unsigned long long mv[7];
#pragma unroll
  for (int n = 0; n < 7; n++) {
    int p = 4 * n + mh;
    mv[n] = (p < 25) ? pack2(Mv0[(2 * p) * DV_ + d], Mv0[(2 * p + 1) * DV_ + d])
                     : 0ULL;
  }

  const size_t row0 = (size_t)b * T_;
  const unsigned* ea_ptr = g_EA + row0 * DV_ + d;
  const float4* wt_ptr = ((const float4*)(g_Wt + row0 * LWP)) + lane;  // lanes<16
  const int* q_ptr = q_data + row0;
  __nv_bfloat16* rd_ptr = g_READ + row0 * DV_ + d;

  const float* wbase = ws + mh * 16;  // pair n at wbase[2n], wbase[2n+1]

  unsigned u = ea_ptr[0];
  int qi = q_ptr[0];
  if (lane < 16) *(float4*)&ws[lane * 4] = wt_ptr[0];
  // same warp produces & consumes ws: program order suffices, no barrier.

  for (int t = 0; t < T_; t++) {
    const int adv = (t + 1 < T_) ? 1 : 0;
    unsigned u2 = ea_ptr[adv * DV_];
    int qi2 = q_ptr[adv];
    float4 wv;
    if (lane < 16) wv = wt_ptr[adv * (LWP / 4)];

    // branchless: q==0 -> ne=av=0 -> mv' = mv exactly
    float msk = (qi >= 1) ? 1.f : 0.f;
    float ne = __uint_as_float(u << 16) * msk;           // stored value is -e
    float av = __uint_as_float(u & 0xFFFF0000u) * msk;
    unsigned long long ne2 = pack2(ne, ne);
    unsigned long long ad2 = pack2(av, av);

    unsigned long long rd0 = 0ULL, rd1 = 0ULL;
#pragma unroll
    for (int n2 = 0; n2 < 3; n2++) {
      ulonglong2 wp = *(const ulonglong2*)&wbase[4 * n2];  // pairs 2n2, 2n2+1
      rd0 = fma2(wp.x, mv[2 * n2], rd0);
      unsigned long long t0 = fma2(mv[2 * n2], ne2, ad2);
      mv[2 * n2] = fma2(wp.x, t0, mv[2 * n2]);
      rd1 = fma2(wp.y, mv[2 * n2 + 1], rd1);
      unsigned long long t1 = fma2(mv[2 * n2 + 1], ne2, ad2);
      mv[2 * n2 + 1] = fma2(wp.y, t1, mv[2 * n2 + 1]);
    }
    if (mh == 0) {  // 7th pair (p=24) at wbase[12..13]
      unsigned long long w = *(const unsigned long long*)&wbase[12];
      rd0 = fma2(w, mv[6], rd0);
      unsigned long long tt = fma2(mv[6], ne2, ad2);
      mv[6] = fma2(w, tt, mv[6]);
    }

    float2 s0 = unpack2(rd0), s1 = unpack2(rd1);
    float sv = (s0.x + s0.y) + (s1.x + s1.y);
    sv += __shfl_xor_sync(0xffffffffu, sv, 1);
    sv += __shfl_xor_sync(0xffffffffu, sv, 2);
    if (mh == 0) *rd_ptr = __float2bfloat16(sv);

    if (lane < 16) *(float4*)&ws[lane * 4] = wv;  // after all ws reads
    u = u2; qi = qi2;
    ea_ptr += DV_;
    wt_ptr += LWP / 4;
    q_ptr += 1;
    rd_ptr += DV_;
  }
  (void)np;
}

// ============ final GEMM (A=[READ|q_e]) cp.async 3-stage + fused head ======
__global__ void __launch_bounds__(256) final_bf16(
    const int* __restrict__ q_data,
    const float* __restrict__ br, const float* __restrict__ Wp,
    const float* __restrict__ bp, const float* __restrict__ target,
    float* __restrict__ out_probs) {
  constexpr int BK = 16, KT = KF_ / BK;
  constexpr int MT = 2, NT = 8;
  constexpr int STGB = 128 * LDT * 2;

  __shared__ __align__(16) __nv_bfloat16 As[3 * 128 * LDT];
  __shared__ __align__(16) __nv_bfloat16 Bs[3 * 128 * LDT];
  __shared__ int rowA[128];
  __shared__ float sBr[128], sWp[128];
  __shared__ float red[128][2];
  __shared__ float sl[128], sv[128];

  const int tid = threadIdx.x;
  const int wid = tid >> 5, lane = tid & 31;
  const int wm = wid >> 1, wn = wid & 1;
  const int r = lane >> 2, c = lane & 3;
  const int bm = blockIdx.y * 128;

  if (tid < 128) { sBr[tid] = br[tid]; sWp[tid] = Wp[tid]; }
  for (int i = tid; i < 128; i += 256) rowA[i] = q_data[bm + i];
  __syncthreads();

  float acc[MT][NT][4];
#pragma unroll
  for (int i = 0; i < MT; i++)
#pragma unroll
    for (int j = 0; j < NT; j++)
#pragma unroll
      for (int q = 0; q < 4; q++) acc[i][j][q] = 0.f;

  const unsigned aBase = smem_u32(As);
  const unsigned bBase = smem_u32(Bs);
  const int gRow = tid >> 1, gHalf = tid & 1;
  const __nv_bfloat16* aSrcR = g_READ + (size_t)(bm + gRow) * DV_ + gHalf * 8;
  const __nv_bfloat16* aSrcQ = g_qt + (size_t)rowA[gRow] * DK_ + gHalf * 8;
  const __nv_bfloat16* bSrc = g_Wr + (size_t)gRow * KF_ + gHalf * 8;
  const unsigned aDst0 = aBase + gRow * 48 + gHalf * 16;
  const unsigned bDst0 = bBase + gRow * 48 + gHalf * 16;

  auto issueT = [&](int kt, int stg) {
    const __nv_bfloat16* a =
        (kt < 16) ? aSrcR + kt * BK : aSrcQ + (kt - 16) * BK;
    cp16(aDst0 + stg * STGB, a);
    cp16(bDst0 + stg * STGB, bSrc + kt * BK);
    CP_COMMIT();
  };

  issueT(0, 0);
  issueT(1, 1);
  CP_WAIT1();
  __syncthreads();

  const int aRow = wm * 32 + (lane & 15);
  const int aColB = (lane & 16) ? 16 : 0;
  const int bRow0 = wn * 64 + ((lane >> 4) << 3) + (lane & 7);
  const int bColB = (lane & 8) ? 16 : 0;

  for (int kt = 0; kt < KT; kt++) {
    const unsigned aS = aBase + (kt % 3) * STGB;
    const unsigned bS = bBase + (kt % 3) * STGB;
    unsigned af[MT][4], bf[NT][2];
#pragma unroll
    for (int mt = 0; mt < MT; mt++)
      ldsm_x4(af[mt][0], af[mt][1], af[mt][2], af[mt][3],
              aS + (aRow + mt * 16) * 48 + aColB);
#pragma unroll
    for (int p = 0; p < 4; p++)
      ldsm_x4(bf[2 * p][0], bf[2 * p][1], bf[2 * p + 1][0], bf[2 * p + 1][1],
              bS + (bRow0 + p * 16) * 48 + bColB);
#pragma unroll
    for (int mt = 0; mt < MT; mt++)
#pragma unroll
      for (int nt = 0; nt < NT; nt++) mma_bf16(acc[mt][nt], af[mt], bf[nt]);
    int nk = (kt + 2 < KT) ? kt + 2 : KT - 1;
    issueT(nk, (kt + 2) % 3);
    CP_WAIT1();
    __syncthreads();
  }

  float ps[4] = {0.f, 0.f, 0.f, 0.f};
#pragma unroll
  for (int nt = 0; nt < NT; nt++) {
#pragma unroll
    for (int j = 0; j < 2; j++) {
      int n = wn * 64 + nt * 8 + 2 * c + j;
      float bb = sBr[n], wp = sWp[n];
#pragma unroll
      for (int mt = 0; mt < MT; mt++) {
        float h0 = tanhf(acc[mt][nt][j] + bb);
        float h1 = tanhf(acc[mt][nt][2 + j] + bb);
        ps[mt * 2 + 0] = fmaf(h0, wp, ps[mt * 2 + 0]);
        ps[mt * 2 + 1] = fmaf(h1, wp, ps[mt * 2 + 1]);
      }
    }
  }
#pragma unroll
  for (int off = 1; off <= 2; off <<= 1)
#pragma unroll
    for (int i = 0; i < 4; i++) ps[i] += __shfl_xor_sync(0xffffffffu, ps[i], off);
  if (c == 0) {
#pragma unroll
    for (int mt = 0; mt < MT; mt++)
#pragma unroll
      for (int hf = 0; hf < 2; hf++)
        red[wm * 32 + mt * 16 + r + hf * 8][wn] = ps[mt * 2 + hf];
  }
  __syncthreads();

  float per = 0.f, val = 0.f;
  if (tid < 128) {
    float p = bp[0] + red[tid][0] + red[tid][1];
    size_t row = (size_t)bm + tid;
    out_probs[row] = 1.f / (1.f + expf(-p));
    float tg = target[row];
    if (tg >= 0.f) {
      per = fmaxf(p, 0.f) - p * tg + log1pf(expf(-fabsf(p)));
      val = 1.f;
    }
  }
  __syncthreads();
  if (tid < 128) { sl[tid] = per; sv[tid] = val; }
  __syncthreads();
  for (int s = 64; s > 0; s >>= 1) {
    if (tid < s) { sl[tid] += sl[tid + s]; sv[tid] += sv[tid + s]; }
    __syncthreads();
  }
  if (tid == 0) {
    g_part[2 * blockIdx.y] = sl[0];
    g_part[2 * blockIdx.y + 1] = sv[0];
  }
}

// ---------------- final loss reduction ----------------
__global__ void __launch_bounds__(256) finalize_kernel(float* __restrict__ out) {
  __shared__ float sl[256], sv[256];
  int tid = threadIdx.x;
  float l = 0.f, v = 0.f;
  for (int i = tid; i < BT_ / 128; i += 256) {
    l += g_part[2 * i];
    v += g_part[2 * i + 1];
  }
  sl[tid] = l; sv[tid] = v;
  __syncthreads();
  for (int s = 128; s > 0; s >>= 1) {
    if (tid < s) { sl[tid] += sl[tid + s]; sv[tid] += sv[tid + s]; }
    __syncthreads();
  }
  if (tid == 0) out[0] = sl[0] / fmaxf(sv[0], 1.f);
}

// ---------------- launch ----------------
extern "C" void kernel_launch(void* const* d_in, const int* in_sizes, int n_in,
                              void* d_out, int out_size) {
  const int* q_data = (const int*)d_in[0];
  const int* qa_data = (const int*)d_in[1];
  const float* target = (const float*)d_in[2];
  const float* q_tab = (const float*)d_in[3];
  const float* qa_tab = (const float*)d_in[4];
  const float* Mk = (const float*)d_in[5];
  const float* Mv0 = (const float*)d_in[6];
  const float* We = (const float*)d_in[7];
  const float* be = (const float*)d_in[8];
  const float* Wa = (const float*)d_in[9];
  const float* ba = (const float*)d_in[10];
  const float* Wr = (const float*)d_in[11];
  const float* br = (const float*)d_in[12];
  const float* Wp = (const float*)d_in[13];
  const float* bp = (const float*)d_in[14];
  float* out = (float*)d_out;

  const long CVT_TOT = (long)NQA * DV_ / 4 + (long)NQT * DK_ / 4 + 16384 +
                       16384 + 12288 + 2048;

  cvt_all<<<(int)((CVT_TOT + 255) / 256), 256>>>(qa_tab, q_tab, We, Wa, Wr, Mk);  // 0
  logits_softmax_bf16<<<BT_ / 128, 256>>>(q_data);                                // 1
  gemm_ea_bf16<<<dim3(4, BT_ / 128), 256>>>(qa_data, be, ba);                     // 2
  scan_kernel<<<B_ * 8, 128>>>(Mv0, q_data);                                      // 3 <- profiled
  final_bf16<<<dim3(1, BT_ / 128), 256>>>(q_data, br, Wp, bp, target, out + 1);   // 4
  finalize_kernel<<<1, 256>>>(out);                                               // 5
}

// round 14
// speedup vs baseline: 1.5504x; 1.5504x over previous
#include <cuda_runtime.h>
#include <cuda_bf16.h>
#include <math.h>

#define B_  256
#define T_  500
#define BT_ 128000
#define DK_ 128
#define DV_ 256
#define M_  50
#define LWP 64    // permuted softmax-weight row stride (floats)
#define KF_ 384
#define LDT 24    // smem tile row stride bf16 (48B, conflict-free ldmatrix)
#define NST 5     // cp.async pipeline stages

#define NQA 100001  // qa_tab rows
#define NQT 50001   // q_tab rows

// ---------------- scratch ----------------
__device__ unsigned g_EA[(size_t)BT_ * DV_];          // (-e, a) bf16x2
__device__ float g_Wt[(size_t)BT_ * LWP];             // permuted softmax weights
__device__ __nv_bfloat16 g_READ[(size_t)BT_ * DV_];
__device__ float g_part[2 * (BT_ / 128)];
__device__ __align__(16) __nv_bfloat16 g_qa[(size_t)NQA * DV_];
__device__ __align__(16) __nv_bfloat16 g_qt[(size_t)NQT * DK_];
__device__ __align__(16) __nv_bfloat16 g_We[DV_ * DV_];
__device__ __align__(16) __nv_bfloat16 g_Wa[DV_ * DV_];
__device__ __align__(16) __nv_bfloat16 g_Wr[DK_ * KF_];
__device__ __align__(16) __nv_bfloat16 g_Mkp[64 * DK_];

// ---------------- helpers ----------------
__device__ __forceinline__ unsigned pack_bf16(float lo, float hi) {
  unsigned r;
  asm("cvt.rn.bf16x2.f32 %0, %1, %2;" : "=r"(r) : "f"(hi), "f"(lo));
  return r;
}
__device__ __forceinline__ void mma_bf16(float* c, const unsigned* a, const unsigned* b) {
  asm volatile(
      "mma.sync.aligned.m16n8k16.row.col.f32.bf16.bf16.f32 "
      "{%0,%1,%2,%3}, {%4,%5,%6,%7}, {%8,%9}, {%0,%1,%2,%3};\n"
      : "+f"(c[0]), "+f"(c[1]), "+f"(c[2]), "+f"(c[3])
      : "r"(a[0]), "r"(a[1]), "r"(a[2]), "r"(a[3]), "r"(b[0]), "r"(b[1]));
}
__device__ __forceinline__ void ldsm_x4(unsigned& r0, unsigned& r1, unsigned& r2,
                                        unsigned& r3, unsigned addr) {
  asm volatile(
      "ldmatrix.sync.aligned.m8n8.x4.shared.b16 {%0,%1,%2,%3}, [%4];"
      : "=r"(r0), "=r"(r1), "=r"(r2), "=r"(r3) : "r"(addr));
}
__device__ __forceinline__ unsigned smem_u32(const void* p) {
  return (unsigned)__cvta_generic_to_shared(p);
}
__device__ __forceinline__ void cp16(unsigned dst, const void* src) {
  asm volatile("cp.async.cg.shared.global [%0], [%1], 16;" :: "r"(dst), "l"(src));
}
#define CP_COMMIT() asm volatile("cp.async.commit_group;")
#define CP_WAIT3()  asm volatile("cp.async.wait_group 3;")

__device__ __forceinline__ unsigned long long pack2(float lo, float hi) {
  unsigned long long r;
  asm("mov.b64 %0, {%1,%2};" : "=l"(r) : "f"(lo), "f"(hi));
  return r;
}
__device__ __forceinline__ unsigned long long fma2(unsigned long long a,
                                                   unsigned long long b,
                                                   unsigned long long c) {
  unsigned long long d;
  asm("fma.rn.f32x2 %0, %1, %2, %3;" : "=l"(d) : "l"(a), "l"(b), "l"(c));
  return d;
}
__device__ __forceinline__ float2 unpack2(unsigned long long v) {
  float2 f;
  asm("mov.b64 {%0,%1}, %2;" : "=f"(f.x), "=f"(f.y) : "l"(v));
  return f;
}

// ---------------- prep: all f32 -> bf16 in ONE launch ----------------
__global__ void __launch_bounds__(256) cvt_all(
    const float* __restrict__ qa, const float* __restrict__ qt,
    const float* __restrict__ We, const float* __restrict__ Wa,
    const float* __restrict__ Wr, const float* __restrict__ Mk) {
  const long N0 = (long)(NQA) * DV_ / 4;
  const long N1 = N0 + (long)(NQT) * DK_ / 4;
  const long N2 = N1 + 16384;
  const long N3 = N2 + 16384;
  const long N4 = N3 + 12288;
  const long N5 = N4 + 2048;
  long i = (long)blockIdx.x * 256 + threadIdx.x;
  if (i >= N5) return;
  const float* src;
  uint2* dst;
  long j;
  if (i < N0) { src = qa; dst = (uint2*)g_qa; j = i; }
  else if (i < N1) { src = qt; dst = (uint2*)g_qt; j = i - N0; }
  else if (i < N2) { src = We; dst = (uint2*)g_We; j = i - N1; }
  else if (i < N3) { src = Wa; dst = (uint2*)g_Wa; j = i - N2; }
  else if (i < N4) { src = Wr; dst = (uint2*)g_Wr; j = i - N3; }
  else {
    j = i - N4;
    float4 v = (j < (M_ * DK_) / 4) ? ((const float4*)Mk)[j]
                                    : make_float4(0.f, 0.f, 0.f, 0.f);
    ((uint2*)g_Mkp)[j] = make_uint2(pack_bf16(v.x, v.y), pack_bf16(v.z, v.w));
    return;
  }
  float4 v = ((const float4*)src)[j];
  dst[j] = make_uint2(pack_bf16(v.x, v.y), pack_bf16(v.z, v.w));
}

// ================= gemm_ea: cp.async 5-stage, E+A one block =================
// stores (-e, a) packed bf16x2
__global__ void __launch_bounds__(256) gemm_ea_bf16(
    const int* __restrict__ idx,
    const float* __restrict__ be, const float* __restrict__ ba) {
  constexpr int BK = 16, KT = DV_ / BK;  // 16
  constexpr int MT = 4;
  constexpr int STGB = 128 * LDT * 2;

  __shared__ __align__(16) __nv_bfloat16 As[NST * 128 * LDT];
  __shared__ __align__(16) __nv_bfloat16 Bs[NST * 128 * LDT];
  __shared__ int rowA[128];

  const int tid = threadIdx.x;
  const int wid = tid >> 5, lane = tid & 31;
  const int wm = wid >> 2, wn = wid & 3;
  const int r = lane >> 2, c = lane & 3;
  const int bm = blockIdx.y * 128;
  const int nrow0 = blockIdx.x * 64;

  for (int i = tid; i < 128; i += 256) rowA[i] = idx[bm + i];
  __syncthreads();

  float accE[MT][2][4], accA[MT][2][4];
#pragma unroll
  for (int i = 0; i < MT; i++)
#pragma unroll
    for (int j = 0; j < 2; j++)
#pragma unroll
      for (int q = 0; q < 4; q++) { accE[i][j][q] = 0.f; accA[i][j][q] = 0.f; }

  const unsigned aBase = smem_u32(As);
  const unsigned bBase = smem_u32(Bs);
  const int gRow = tid >> 1, gHalf = tid & 1;
  const __nv_bfloat16* aSrc = g_qa + (size_t)rowA[gRow] * DV_ + gHalf * 8;
  const __nv_bfloat16* bSrc =
      (gRow < 64) ? g_We + (size_t)(nrow0 + gRow) * DV_ + gHalf * 8
                  : g_Wa + (size_t)(nrow0 + gRow - 64) * DV_ + gHalf * 8;
  const unsigned aDst0 = aBase + gRow * 48 + gHalf * 16;
  const unsigned bDst0 = bBase + gRow * 48 + gHalf * 16;

  auto issueT = [&](int kt, int stg) {
    cp16(aDst0 + stg * STGB, aSrc + kt * BK);
    cp16(bDst0 + stg * STGB, bSrc + kt * BK);
    CP_COMMIT();
  };

  issueT(0, 0);
  issueT(1, 1);
  issueT(2, 2);
  issueT(3, 3);
  CP_WAIT3();
  __syncthreads();

  const int aRow = wm * 64 + (lane & 15);
  const int aColB = (lane & 16) ? 16 : 0;
  const int bRowE = wn * 16 + ((lane >> 4) << 3) + (lane & 7);
  const int bColB = (lane & 8) ? 16 : 0;

  for (int kt = 0; kt < KT; kt++) {
    const unsigned aS = aBase + (kt % NST) * STGB;
    const unsigned bS = bBase + (kt % NST) * STGB;
    unsigned af[MT][4], bfe[4], bfa[4];
#pragma unroll
    for (int mt = 0; mt < MT; mt++)
      ldsm_x4(af[mt][0], af[mt][1], af[mt][2], af[mt][3],
              aS + (aRow + mt * 16) * 48 + aColB);
    ldsm_x4(bfe[0], bfe[1], bfe[2], bfe[3], bS + bRowE * 48 + bColB);
    ldsm_x4(bfa[0], bfa[1], bfa[2], bfa[3], bS + (64 + bRowE) * 48 + bColB);
#pragma unroll
    for (int mt = 0; mt < MT; mt++) {
      mma_bf16(accE[mt][0], af[mt], &bfe[0]);
      mma_bf16(accE[mt][1], af[mt], &bfe[2]);
      mma_bf16(accA[mt][0], af[mt], &bfa[0]);
      mma_bf16(accA[mt][1], af[mt], &bfa[2]);
    }
    int nk = (kt + 4 < KT) ? kt + 4 : KT - 1;
    issueT(nk, (kt + 4) % NST);
    CP_WAIT3();
    __syncthreads();
  }

#pragma unroll
  for (int mt = 0; mt < MT; mt++) {
#pragma unroll
    for (int nt = 0; nt < 2; nt++) {
      int rowL = wm * 64 + mt * 16 + r;
      int ncol = nrow0 + wn * 16 + nt * 8 + 2 * c;
      float be0 = be[ncol], be1 = be[ncol + 1];
      float ba0 = ba[ncol], ba1 = ba[ncol + 1];
      float e0 = 1.f / (1.f + expf(-(accE[mt][nt][0] + be0)));
      float e1 = 1.f / (1.f + expf(-(accE[mt][nt][1] + be1)));
      float e2 = 1.f / (1.f + expf(-(accE[mt][nt][2] + be0)));
      float e3 = 1.f / (1.f + expf(-(accE[mt][nt][3] + be1)));
      float a0 = tanhf(accA[mt][nt][0] + ba0);
      float a1 = tanhf(accA[mt][nt][1] + ba1);
      float a2 = tanhf(accA[mt][nt][2] + ba0);
      float a3 = tanhf(accA[mt][nt][3] + ba1);
      *(uint2*)(g_EA + (size_t)(bm + rowL) * DV_ + ncol) =
          make_uint2(pack_bf16(-e0, a0), pack_bf16(-e1, a1));
      *(uint2*)(g_EA + (size_t)(bm + rowL + 8) * DV_ + ncol) =
          make_uint2(pack_bf16(-e2, a2), pack_bf16(-e3, a3));
    }
  }
}

// ================= logits GEMM + softmax: 5-stage, permuted-w output =========
// g_Wt row layout (64 floats): [even pairs: j=4s+o at pos 2s+o, s<13 -> 0..25]
// [pad 26..31] [odd pairs: j=4s+2+o at pos 32+2s+o, s<12 -> 32..55] [pad 56..63]
__global__ void __launch_bounds__(256) logits_softmax_bf16(
    const int* __restrict__ q_data) {
  constexpr int BK = 16, KT = DK_ / BK;  // 8
  constexpr int MT = 2, NT = 4;
  constexpr int STGA = 128 * LDT * 2;
  constexpr int STGB = 64 * LDT * 2;

  __shared__ __align__(16) __nv_bfloat16 As[NST * 128 * LDT];
  __shared__ __align__(16) __nv_bfloat16 Bs[NST * 64 * LDT];
  __shared__ int rowA[128];
  __shared__ float sLg[128][65];
  __shared__ float sInv[128];

  const int tid = threadIdx.x;
  const int wid = tid >> 5, lane = tid & 31;
  const int wm = wid >> 1, wn = wid & 1;
  const int r = lane >> 2, c = lane & 3;
  const int bm = blockIdx.x * 128;

  for (int i = tid; i < 128; i += 256) rowA[i] = q_data[bm + i];
  __syncthreads();

  float acc[MT][NT][4];
#pragma unroll
  for (int i = 0; i < MT; i++)
#pragma unroll
    for (int j = 0; j < NT; j++)
#pragma unroll
      for (int q = 0; q < 4; q++) acc[i][j][q] = 0.f;

  const unsigned aBase = smem_u32(As);
  const unsigned bBase = smem_u32(Bs);
  const int gRow = tid >> 1, gHalf = tid & 1;
  const __nv_bfloat16* aSrc = g_qt + (size_t)rowA[gRow] * DK_ + gHalf * 8;
  const __nv_bfloat16* bSrc = g_Mkp + (size_t)gRow * DK_ + gHalf * 8;
  const unsigned aDst0 = aBase + gRow * 48 + gHalf * 16;
  const unsigned bDst0 = bBase + gRow * 48 + gHalf * 16;

  auto issueT = [&](int kt, int stg) {
    cp16(aDst0 + stg * STGA, aSrc + kt * BK);
    if (tid < 128) cp16(bDst0 + stg * STGB, bSrc + kt * BK);
    CP_COMMIT();
  };

  issueT(0, 0);
  issueT(1, 1);
  issueT(2, 2);
  issueT(3, 3);
  CP_WAIT3();
  __syncthreads();

  const int aRow = wm * 32 + (lane & 15);
  const int aColB = (lane & 16) ? 16 : 0;
  const int bRow0 = wn * 32 + ((lane >> 4) << 3) + (lane & 7);
  const int bColB = (lane & 8) ? 16 : 0;

  for (int kt = 0; kt < KT; kt++) {
    const unsigned aS = aBase + (kt % NST) * STGA;
    const unsigned bS = bBase + (kt % NST) * STGB;
    unsigned af[MT][4], bf[NT][2];
#pragma unroll
    for (int mt = 0; mt < MT; mt++)
      ldsm_x4(af[mt][0], af[mt][1], af[mt][2], af[mt][3],
              aS + (aRow + mt * 16) * 48 + aColB);
#pragma unroll
    for (int p = 0; p < 2; p++)
      ldsm_x4(bf[2 * p][0], bf[2 * p][1], bf[2 * p + 1][0], bf[2 * p + 1][1],
              bS + (bRow0 + p * 16) * 48 + bColB);
#pragma unroll
    for (int mt = 0; mt < MT; mt++)
#pragma unroll
      for (int nt = 0; nt < NT; nt++) mma_bf16(acc[mt][nt], af[mt], bf[nt]);
    int nk = (kt + 4 < KT) ? kt + 4 : KT - 1;
    issueT(nk, (kt + 4) % NST);
    CP_WAIT3();
    __syncthreads();
  }

#pragma unroll
  for (int mt = 0; mt < MT; mt++) {
#pragma unroll
    for (int nt = 0; nt < NT; nt++) {
      int rowL = wm * 32 + mt * 16 + r;
      int colL = wn * 32 + nt * 8 + 2 * c;
      sLg[rowL][colL] = acc[mt][nt][0];
      sLg[rowL][colL + 1] = acc[mt][nt][1];
      sLg[rowL + 8][colL] = acc[mt][nt][2];
      sLg[rowL + 8][colL + 1] = acc[mt][nt][3];
    }
  }
  __syncthreads();

  if (tid < 128) {
    float mx = -1e30f;
#pragma unroll 10
    for (int j = 0; j < M_; j++) mx = fmaxf(mx, sLg[tid][j]);
    float s = 0.f;
#pragma unroll 10
    for (int j = 0; j < M_; j++) {
      float ev = expf(sLg[tid][j] - mx);
      sLg[tid][j] = ev;
      s += ev;
    }
    sInv[tid] = 1.f / s;
  }
  __syncthreads();

  // permuted coalesced write (pads = 0)
  for (int f = tid; f < 128 * LWP; f += 256) {
    int rowL = f >> 6;
    int pos = f & 63;
    int j = -1;
    if (pos < 26) j = ((pos >> 1) << 2) + (pos & 1);
    else if (pos >= 32 && pos < 56) j = (((pos - 32) >> 1) << 2) + 2 + (pos & 1);
    float v = (j >= 0) ? sLg[rowL][j] * sInv[rowL] : 0.f;
    g_Wt[(size_t)(bm + rowL) * LWP + pos] = v;
  }
}

// ------- scan: m-split x2, branchless, permuted contiguous w reads (R12) -----
__global__ void __launch_bounds__(128, 8) scan_kernel(
    const float* __restrict__ Mv0, const int* __restrict__ q_data) {
  const int b = blockIdx.x >> 2;
  const int dseg = blockIdx.x & 3;
  const int tid = threadIdx.x;
  const int wid = tid >> 5, lane = tid & 31;
  const int d = dseg * 64 + (tid >> 1);
  const int mh = tid & 1;
  __shared__ __align__(16) float ws_all[4][64];
  float* ws = ws_all[wid];

  // mv[n] = pair (2n + mh); mh0 additionally owns pair 24 in mv[12]
  unsigned long long mv[13];
#pragma unroll
  for (int n = 0; n < 12; n++) {
    int m0 = (2 * n + mh) * 2;
    mv[n] = pack2(Mv0[m0 * DV_ + d], Mv0[(m0 + 1) * DV_ + d]);
  }
  mv[12] = (mh == 0) ? pack2(Mv0[48 * DV_ + d], Mv0[49 * DV_ + d]) : 0ULL;

  const size_t row0 = (size_t)b * T_;
  const unsigned* ea_ptr = g_EA + row0 * DV_ + d;
  const float4* wt_ptr = ((const float4*)(g_Wt + row0 * LWP)) + lane;  // lanes<16
  const int* q_ptr = q_data + row0;
  __nv_bfloat16* rd_ptr = g_READ + row0 * DV_ + d;

  // contiguous owned-w base: mh0 at ws[0], mh1 at ws[32]; pair n at base+2n
  const float* wbase = ws + mh * 32;

  unsigned u = ea_ptr[0];
  int qi = q_ptr[0];
  if (lane < 16) *(float4*)&ws[lane * 4] = wt_ptr[0];
  // same warp produces & consumes ws: program order suffices, no barrier.

  for (int t = 0; t < T_; t++) {
    const int adv = (t + 1 < T_) ? 1 : 0;
    unsigned u2 = ea_ptr[adv * DV_];
    int qi2 = q_ptr[adv];
    float4 wv;
    if (lane < 16) wv = wt_ptr[adv * (LWP / 4)];

    // branchless: q==0 -> ne=av=0 -> mv' = fma2(w, 0, mv) = mv exactly
    float msk = (qi >= 1) ? 1.f : 0.f;
    float ne = __uint_as_float(u << 16) * msk;           // stored value is -e
    float av = __uint_as_float(u & 0xFFFF0000u) * msk;
    unsigned long long ne2 = pack2(ne, ne);
    unsigned long long ad2 = pack2(av, av);

    unsigned long long rd0 = 0ULL, rd1 = 0ULL;
#pragma unroll
    for (int n = 0; n < 6; n++) {
      ulonglong2 wp = *(const ulonglong2*)&wbase[4 * n];  // pairs 2n, 2n+1
      rd0 = fma2(wp.x, mv[2 * n], rd0);
      unsigned long long t0 = fma2(mv[2 * n], ne2, ad2);
      mv[2 * n] = fma2(wp.x, t0, mv[2 * n]);
      rd1 = fma2(wp.y, mv[2 * n + 1], rd1);
      unsigned long long t1 = fma2(mv[2 * n + 1], ne2, ad2);
      mv[2 * n + 1] = fma2(wp.y, t1, mv[2 * n + 1]);
    }
    if (mh == 0) {  // pair 24 at ws[24]
      unsigned long long w = *(const unsigned long long*)&ws[24];
      rd0 = fma2(w, mv[12], rd0);
      unsigned long long tt = fma2(mv[12], ne2, ad2);
      mv[12] = fma2(w, tt, mv[12]);
    }

    float2 s0 = unpack2(rd0), s1 = unpack2(rd1);
    float sv = (s0.x + s0.y) + (s1.x + s1.y);
    sv += __shfl_xor_sync(0xffffffffu, sv, 1);
    if (mh == 0) *rd_ptr = __float2bfloat16(sv);

    if (lane < 16) *(float4*)&ws[lane * 4] = wv;  // after all ws reads
    u = u2; qi = qi2;
    ea_ptr += DV_;
    wt_ptr += LWP / 4;
    q_ptr += 1;
    rd_ptr += DV_;
  }
}

// ============ final GEMM (A=[READ|q_e]) cp.async 5-stage + fused head ======
__global__ void __launch_bounds__(256) final_bf16(
    const int* __restrict__ q_data,
    const float* __restrict__ br, const float* __restrict__ Wp,
    const float* __restrict__ bp, const float* __restrict__ target,
    float* __restrict__ out_probs) {
  constexpr int BK = 16, KT = KF_ / BK;  // 24
  constexpr int MT = 2, NT = 8;
  constexpr int STGB = 128 * LDT * 2;

  __shared__ __align__(16) __nv_bfloat16 As[NST * 128 * LDT];
  __shared__ __align__(16) __nv_bfloat16 Bs[NST * 128 * LDT];
  __shared__ int rowA[128];
  __shared__ float sBr[128], sWp[128];
  __shared__ float red[128][2];
  __shared__ float sl[128], sv[128];

  const int tid = threadIdx.x;
  const int wid = tid >> 5, lane = tid & 31;
  const int wm = wid >> 1, wn = wid & 1;
  const int r = lane >> 2, c = lane & 3;
  const int bm = blockIdx.y * 128;

  if (tid < 128) { sBr[tid] = br[tid]; sWp[tid] = Wp[tid]; }
  for (int i = tid; i < 128; i += 256) rowA[i] = q_data[bm + i];
  __syncthreads();

  float acc[MT][NT][4];
#pragma unroll
  for (int i = 0; i < MT; i++)
#pragma unroll
    for (int j = 0; j < NT; j++)
#pragma unroll
      for (int q = 0; q < 4; q++) acc[i][j][q] = 0.f;

  const unsigned aBase = smem_u32(As);
  const unsigned bBase = smem_u32(Bs);
  const int gRow = tid >> 1, gHalf = tid & 1;
  const __nv_bfloat16* aSrcR = g_READ + (size_t)(bm + gRow) * DV_ + gHalf * 8;
  const __nv_bfloat16* aSrcQ = g_qt + (size_t)rowA[gRow] * DK_ + gHalf * 8;
  const __nv_bfloat16* bSrc = g_Wr + (size_t)gRow * KF_ + gHalf * 8;
  const unsigned aDst0 = aBase + gRow * 48 + gHalf * 16;
  const unsigned bDst0 = bBase + gRow * 48 + gHalf * 16;

  auto issueT = [&](int kt, int stg) {
    const __nv_bfloat16* a =
        (kt < 16) ? aSrcR + kt * BK : aSrcQ + (kt - 16) * BK;
    cp16(aDst0 + stg * STGB, a);
    cp16(bDst0 + stg * STGB, bSrc + kt * BK);
    CP_COMMIT();
  };

  issueT(0, 0);
  issueT(1, 1);
  issueT(2, 2);
  issueT(3, 3);
  CP_WAIT3();
  __syncthreads();

  const int aRow = wm * 32 + (lane & 15);
  const int aColB = (lane & 16) ? 16 : 0;
  const int bRow0 = wn * 64 + ((lane >> 4) << 3) + (lane & 7);
  const int bColB = (lane & 8) ? 16 : 0;

  for (int kt = 0; kt < KT; kt++) {
    const unsigned aS = aBase + (kt % NST) * STGB;
    const unsigned bS = bBase + (kt % NST) * STGB;
    unsigned af[MT][4], bf[NT][2];
#pragma unroll
    for (int mt = 0; mt < MT; mt++)
      ldsm_x4(af[mt][0], af[mt][1], af[mt][2], af[mt][3],
              aS + (aRow + mt * 16) * 48 + aColB);
#pragma unroll
    for (int p = 0; p < 4; p++)
      ldsm_x4(bf[2 * p][0], bf[2 * p][1], bf[2 * p + 1][0], bf[2 * p + 1][1],
              bS + (bRow0 + p * 16) * 48 + bColB);
#pragma unroll
    for (int mt = 0; mt < MT; mt++)
#pragma unroll
      for (int nt = 0; nt < NT; nt++) mma_bf16(acc[mt][nt], af[mt], bf[nt]);
    int nk = (kt + 4 < KT) ? kt + 4 : KT - 1;
    issueT(nk, (kt + 4) % NST);
    CP_WAIT3();
    __syncthreads();
  }

  float ps[4] = {0.f, 0.f, 0.f, 0.f};
#pragma unroll
  for (int nt = 0; nt < NT; nt++) {
#pragma unroll
    for (int j = 0; j < 2; j++) {
      int n = wn * 64 + nt * 8 + 2 * c + j;
      float bb = sBr[n], wp = sWp[n];
#pragma unroll
      for (int mt = 0; mt < MT; mt++) {
        float h0 = tanhf(acc[mt][nt][j] + bb);
        float h1 = tanhf(acc[mt][nt][2 + j] + bb);
        ps[mt * 2 + 0] = fmaf(h0, wp, ps[mt * 2 + 0]);
        ps[mt * 2 + 1] = fmaf(h1, wp, ps[mt * 2 + 1]);
      }
    }
  }
#pragma unroll
  for (int off = 1; off <= 2; off <<= 1)
#pragma unroll
    for (int i = 0; i < 4; i++) ps[i] += __shfl_xor_sync(0xffffffffu, ps[i], off);
  if (c == 0) {
#pragma unroll
    for (int mt = 0; mt < MT; mt++)
#pragma unroll
      for (int hf = 0; hf < 2; hf++)
        red[wm * 32 + mt * 16 + r + hf * 8][wn] = ps[mt * 2 + hf];
  }
  __syncthreads();

  float per = 0.f, val = 0.f;
  if (tid < 128) {
    float p = bp[0] + red[tid][0] + red[tid][1];
    size_t row = (size_t)bm + tid;
    out_probs[row] = 1.f / (1.f + expf(-p));
    float tg = target[row];
    if (tg >= 0.f) {
      per = fmaxf(p, 0.f) - p * tg + log1pf(expf(-fabsf(p)));
      val = 1.f;
    }
  }
  __syncthreads();
  if (tid < 128) { sl[tid] = per; sv[tid] = val; }
  __syncthreads();
  for (int s = 64; s > 0; s >>= 1) {
    if (tid < s) { sl[tid] += sl[tid + s]; sv[tid] += sv[tid + s]; }
    __syncthreads();
  }
  if (tid == 0) {
    g_part[2 * blockIdx.y] = sl[0];
    g_part[2 * blockIdx.y + 1] = sv[0];
  }
}

// ---------------- final loss reduction ----------------
__global__ void __launch_bounds__(256) finalize_kernel(float* __restrict__ out) {
  __shared__ float sl[256], sv[256];
  int tid = threadIdx.x;
  float l = 0.f, v = 0.f;
  for (int i = tid; i < BT_ / 128; i += 256) {
    l += g_part[2 * i];
    v += g_part[2 * i + 1];
  }
  sl[tid] = l; sv[tid] = v;
  __syncthreads();
  for (int s = 128; s > 0; s >>= 1) {
    if (tid < s) { sl[tid] += sl[tid + s]; sv[tid] += sv[tid + s]; }
    __syncthreads();
  }
  if (tid == 0) out[0] = sl[0] / fmaxf(sv[0], 1.f);
}

// ---------------- launch ----------------
extern "C" void kernel_launch(void* const* d_in, const int* in_sizes, int n_in,
                              void* d_out, int out_size) {
  const int* q_data = (const int*)d_in[0];
  const int* qa_data = (const int*)d_in[1];
  const float* target = (const float*)d_in[2];
  const float* q_tab = (const float*)d_in[3];
  const float* qa_tab = (const float*)d_in[4];
  const float* Mk = (const float*)d_in[5];
  const float* Mv0 = (const float*)d_in[6];
  const float* We = (const float*)d_in[7];
  const float* be = (const float*)d_in[8];
  const float* Wa = (const float*)d_in[9];
  const float* ba = (const float*)d_in[10];
  const float* Wr = (const float*)d_in[11];
  const float* br = (const float*)d_in[12];
  const float* Wp = (const float*)d_in[13];
  const float* bp = (const float*)d_in[14];
  float* out = (float*)d_out;

  const long CVT_TOT = (long)NQA * DV_ / 4 + (long)NQT * DK_ / 4 + 16384 +
                       16384 + 12288 + 2048;

  cvt_all<<<(int)((CVT_TOT + 255) / 256), 256>>>(qa_tab, q_tab, We, Wa, Wr, Mk);  // 0
  logits_softmax_bf16<<<BT_ / 128, 256>>>(q_data);                                // 1
  gemm_ea_bf16<<<dim3(4, BT_ / 128), 256>>>(qa_data, be, ba);                     // 2
  scan_kernel<<<B_ * 4, 128>>>(Mv0, q_data);                                      // 3 <- profiled
  final_bf16<<<dim3(1, BT_ / 128), 256>>>(q_data, br, Wp, bp, target, out + 1);   // 4
  finalize_kernel<<<1, 256>>>(out);                                               // 5
}